// round 9
// baseline (speedup 1.0000x reference)
#include <cuda_runtime.h>
#include <cstdint>
#include <cstddef>

#define D 128
#define MAXN 100000
#define MAXE 1600000
#define BM 64
#define RSTR 66          // float stride: row-pairs 8B-aligned, LDS.64 conflict-free
#define SCHUNK 1024
#define NBLK_SCAN 98     // ceil((MAXN+1)/SCHUNK); < 148 SMs => co-resident

typedef unsigned long long u64;

// ---------------------------------------------------------------------------
// Device scratch (static; allocation-guard-safe). Zero-initialized at load.
// g_cnt is re-zeroed by histscan phase 3 each launch; g_bar is monotonic.
// ---------------------------------------------------------------------------
__device__ float g_agg[(size_t)MAXN * D];
__device__ u64   g_edges[MAXE];
__device__ int   g_cnt[MAXN];
__device__ int   g_row[MAXN + 1];
__device__ int   g_cur[MAXN];
__device__ int   g_look[NBLK_SCAN];
__device__ unsigned g_bar;                     // monotonic grid-barrier counter

// ---------------------------------------------------------------------------
// f32x2 helpers
// ---------------------------------------------------------------------------
__device__ __forceinline__ u64 dup2(float f) {
    u64 r; unsigned u = __float_as_uint(f);
    asm("mov.b64 %0, {%1, %1};" : "=l"(r) : "r"(u));
    return r;
}
__device__ __forceinline__ void ffma2(u64& d, u64 a, u64 b) {
    asm("fma.rn.f32x2 %0, %1, %2, %0;" : "+l"(d) : "l"(a), "l"(b));
}
__device__ __forceinline__ u64 add2(u64 a, u64 b) {
    u64 r;
    asm("add.rn.f32x2 %0, %1, %2;" : "=l"(r) : "l"(a), "l"(b));
    return r;
}

// per-block index-dtype sniff (int64 indices < 100000 → odd words all zero)
__device__ __forceinline__ bool block_sniff64(const int* p, int* s_flag) {
    if (threadIdx.x == 0) {
        unsigned o = 0;
        #pragma unroll
        for (int j = 0; j < 16; j++) o |= (unsigned)p[2 * j + 1];
        *s_flag = (o == 0u) ? 1 : 0;
    }
    __syncthreads();
    return *s_flag != 0;
}

// software grid barrier for a co-resident grid of `nb` blocks.
// Monotonic counter => safe across launches/replays; release/acquire ordered.
__device__ __forceinline__ void grid_barrier(int nb) {
    __syncthreads();
    if (threadIdx.x == 0) {
        __threadfence();
        unsigned my = atomicAdd(&g_bar, 1u);
        unsigned target = (my / nb + 1u) * (unsigned)nb;
        unsigned cur;
        do {
            asm volatile("ld.acquire.gpu.global.u32 %0, [%1];"
                         : "=r"(cur) : "l"(&g_bar) : "memory");
        } while (cur < target);
    }
    __syncthreads();
}

// ---------------------------------------------------------------------------
// Launch 1: histogram + exclusive scan in ONE kernel (98 co-resident blocks)
//   phase 1: edge histogram (grid-strided)
//   phase 2: per-chunk totals -> g_look
//   phase 3: cross-chunk prefix + emit g_row/g_cur, re-zero g_cnt
// ---------------------------------------------------------------------------
__global__ void __launch_bounds__(256) histscan_kernel(const int* __restrict__ dst_raw,
                                                       int n, int E) {
    __shared__ int s_is64;
    __shared__ int wsum[8];
    __shared__ int s_red[256];
    __shared__ int s_prefix;

    const int tid  = threadIdx.x;
    const int lane = tid & 31;
    const int wid  = tid >> 5;
    const int b    = blockIdx.x;
    const int nb   = gridDim.x;

    // -- phase 1: histogram
    const bool is64 = block_sniff64(dst_raw, &s_is64);
    if (is64) {
        const long long* d64 = (const long long*)dst_raw;
        for (int e = b * 256 + tid; e < E; e += nb * 256)
            atomicAdd(&g_cnt[(int)d64[e]], 1);
    } else {
        for (int e = b * 256 + tid; e < E; e += nb * 256)
            atomicAdd(&g_cnt[dst_raw[e]], 1);
    }
    grid_barrier(nb);

    // -- phase 2: block-local scan of this block's SCHUNK nodes
    const int base = b * SCHUNK + tid * 4;
    int v[4];
    #pragma unroll
    for (int j = 0; j < 4; j++)
        v[j] = (base + j < n) ? g_cnt[base + j] : 0;
    int s = v[0] + v[1] + v[2] + v[3];

    int inc = s;
    #pragma unroll
    for (int off = 1; off < 32; off <<= 1) {
        int t = __shfl_up_sync(0xffffffffu, inc, off);
        if (lane >= off) inc += t;
    }
    if (lane == 31) wsum[wid] = inc;
    __syncthreads();
    if (wid == 0) {
        int wv = (lane < 8) ? wsum[lane] : 0;
        #pragma unroll
        for (int off = 1; off < 8; off <<= 1) {
            int t = __shfl_up_sync(0xffffffffu, wv, off);
            if (lane >= off) wv += t;
        }
        if (lane < 8) wsum[lane] = wv;
    }
    __syncthreads();
    if (tid == 0) g_look[b] = wsum[7];          // chunk total
    grid_barrier(nb);

    // -- phase 3: cross-chunk prefix (reduce predecessors), emit, re-zero cnt
    s_red[tid] = (tid < b) ? g_look[tid] : 0;
    __syncthreads();
    for (int off = 128; off > 0; off >>= 1) {
        if (tid < off) s_red[tid] += s_red[tid + off];
        __syncthreads();
    }
    if (tid == 0) s_prefix = s_red[0];
    __syncthreads();

    int excl = inc - s + (wid > 0 ? wsum[wid - 1] : 0) + s_prefix;
    #pragma unroll
    for (int j = 0; j < 4; j++) {
        int idx = base + j;
        if (idx <= n) {
            g_row[idx] = excl;
            if (idx < n) { g_cur[idx] = excl; g_cnt[idx] = 0; }
        }
        excl += v[j];
    }
}

// ---------------------------------------------------------------------------
// Launch 2: scatter packed (w,src) into CSR order
// ---------------------------------------------------------------------------
__global__ void __launch_bounds__(256) scatter_kernel(const int* __restrict__ src_raw,
                                                      const int* __restrict__ dst_raw,
                                                      const float* __restrict__ w, int E) {
    __shared__ int s_is64;
    const bool is64 = block_sniff64(dst_raw, &s_is64);
    int t = blockIdx.x * blockDim.x + threadIdx.x;
    int e = t * 2;
    if (e >= E) return;
    int cnt = min(2, E - e);
    #pragma unroll
    for (int j = 0; j < 2; j++) {
        if (j >= cnt) break;
        int s, d;
        if (is64) {
            s = (int)((const long long*)src_raw)[e + j];
            d = (int)((const long long*)dst_raw)[e + j];
        } else {
            s = src_raw[e + j];
            d = dst_raw[e + j];
        }
        float ww = w[e + j];
        int pos = atomicAdd(&g_cur[d], 1);
        g_edges[pos] = ((u64)__float_as_uint(ww) << 32) | (unsigned)s;
    }
}

// ---------------------------------------------------------------------------
// Launch 3: aggregation (unchanged from R8 — known 81 us)
// ---------------------------------------------------------------------------
__global__ void __launch_bounds__(256) agg_kernel(const float* __restrict__ x, int n) {
    const int warp = (blockIdx.x * blockDim.x + threadIdx.x) >> 5;
    if (warp >= n) return;
    const int lane = threadIdx.x & 31;

    const int beg = g_row[warp];
    const int end = g_row[warp + 1];
    const float4* x4 = (const float4*)x;

    float4 a0 = make_float4(0.f, 0.f, 0.f, 0.f);
    float4 a1 = make_float4(0.f, 0.f, 0.f, 0.f);
    float4 a2 = make_float4(0.f, 0.f, 0.f, 0.f);
    float4 a3 = make_float4(0.f, 0.f, 0.f, 0.f);

    int i = beg;
    for (; i + 3 < end; i += 4) {
        u64 e0 = g_edges[i];
        u64 e1 = g_edges[i + 1];
        u64 e2 = g_edges[i + 2];
        u64 e3 = g_edges[i + 3];
        float4 v0 = __ldg(&x4[(size_t)(unsigned)e0 * (D / 4) + lane]);
        float4 v1 = __ldg(&x4[(size_t)(unsigned)e1 * (D / 4) + lane]);
        float4 v2 = __ldg(&x4[(size_t)(unsigned)e2 * (D / 4) + lane]);
        float4 v3 = __ldg(&x4[(size_t)(unsigned)e3 * (D / 4) + lane]);
        float w0 = __uint_as_float((unsigned)(e0 >> 32));
        float w1 = __uint_as_float((unsigned)(e1 >> 32));
        float w2 = __uint_as_float((unsigned)(e2 >> 32));
        float w3 = __uint_as_float((unsigned)(e3 >> 32));
        a0.x += w0 * v0.x; a0.y += w0 * v0.y; a0.z += w0 * v0.z; a0.w += w0 * v0.w;
        a1.x += w1 * v1.x; a1.y += w1 * v1.y; a1.z += w1 * v1.z; a1.w += w1 * v1.w;
        a2.x += w2 * v2.x; a2.y += w2 * v2.y; a2.z += w2 * v2.z; a2.w += w2 * v2.w;
        a3.x += w3 * v3.x; a3.y += w3 * v3.y; a3.z += w3 * v3.z; a3.w += w3 * v3.w;
    }
    for (; i < end; i++) {
        u64 e0 = g_edges[i];
        float w0 = __uint_as_float((unsigned)(e0 >> 32));
        float4 v0 = __ldg(&x4[(size_t)(unsigned)e0 * (D / 4) + lane]);
        a0.x += w0 * v0.x; a0.y += w0 * v0.y; a0.z += w0 * v0.z; a0.w += w0 * v0.w;
    }
    float4 r;
    r.x = (a0.x + a1.x) + (a2.x + a3.x);
    r.y = (a0.y + a1.y) + (a2.y + a3.y);
    r.z = (a0.z + a1.z) + (a2.z + a3.z);
    r.w = (a0.w + a1.w) + (a2.w + a3.w);
    ((float4*)g_agg)[(size_t)warp * (D / 4) + lane] = r;
}

// ---------------------------------------------------------------------------
// Launch 4 (PROFILED SLOT): dual GEMM  out = agg @ Wn + x @ Ws + bias
// (byte-identical math to R8 — this round is about getting its profile)
// ---------------------------------------------------------------------------
__global__ void __launch_bounds__(256, 2) dual_gemm_kernel(
    const float* __restrict__ x,
    const float* __restrict__ Wn,
    const float* __restrict__ Ws,
    const float* __restrict__ bias,
    float* __restrict__ out, int n)
{
    extern __shared__ float sm[];
    float* s_a = sm;                  // [128][RSTR] agg tile
    float* s_x = sm + 128 * RSTR;     // x tile

    const int tid = threadIdx.x;
    const int row0 = blockIdx.x * BM;

    for (int idx = tid; idx < BM * D; idx += 256) {
        int r = idx >> 7;
        int k = idx & 127;
        int gr = row0 + r;
        float av = 0.f, xv = 0.f;
        if (gr < n) {
            av = g_agg[(size_t)gr * D + k];
            xv = x[(size_t)gr * D + k];
        }
        s_a[k * RSTR + r] = av;
        s_x[k * RSTR + r] = xv;
    }
    __syncthreads();

    const int c0 = (tid >> 5) * 16;   // warp -> 16-col slab
    const int r0 = (tid & 31) * 2;    // lane -> row pair

    u64 acc0[8], acc1[8];
    #pragma unroll
    for (int c = 0; c < 8; c++) { acc0[c] = 0ull; acc1[c] = 0ull; }

    #pragma unroll 2
    for (int k = 0; k < 128; k++) {
        float2 ap = *(const float2*)(s_a + k * RSTR + r0);
        float2 xp = *(const float2*)(s_x + k * RSTR + r0);
        u64 A0 = dup2(ap.x), A1 = dup2(ap.y);
        u64 X0 = dup2(xp.x), X1 = dup2(xp.y);

        const ulonglong2* pn = (const ulonglong2*)(Wn + (size_t)k * D + c0);
        const ulonglong2* ps = (const ulonglong2*)(Ws + (size_t)k * D + c0);
        ulonglong2 n01 = __ldg(pn);
        ulonglong2 n23 = __ldg(pn + 1);
        ulonglong2 n45 = __ldg(pn + 2);
        ulonglong2 n67 = __ldg(pn + 3);
        ulonglong2 s01 = __ldg(ps);
        ulonglong2 s23 = __ldg(ps + 1);
        ulonglong2 s45 = __ldg(ps + 2);
        ulonglong2 s67 = __ldg(ps + 3);

        ffma2(acc0[0], A0, n01.x); ffma2(acc0[0], X0, s01.x);
        ffma2(acc0[1], A0, n01.y); ffma2(acc0[1], X0, s01.y);
        ffma2(acc0[2], A0, n23.x); ffma2(acc0[2], X0, s23.x);
        ffma2(acc0[3], A0, n23.y); ffma2(acc0[3], X0, s23.y);
        ffma2(acc0[4], A0, n45.x); ffma2(acc0[4], X0, s45.x);
        ffma2(acc0[5], A0, n45.y); ffma2(acc0[5], X0, s45.y);
        ffma2(acc0[6], A0, n67.x); ffma2(acc0[6], X0, s67.x);
        ffma2(acc0[7], A0, n67.y); ffma2(acc0[7], X0, s67.y);

        ffma2(acc1[0], A1, n01.x); ffma2(acc1[0], X1, s01.x);
        ffma2(acc1[1], A1, n01.y); ffma2(acc1[1], X1, s01.y);
        ffma2(acc1[2], A1, n23.x); ffma2(acc1[2], X1, s23.x);
        ffma2(acc1[3], A1, n23.y); ffma2(acc1[3], X1, s23.y);
        ffma2(acc1[4], A1, n45.x); ffma2(acc1[4], X1, s45.x);
        ffma2(acc1[5], A1, n45.y); ffma2(acc1[5], X1, s45.y);
        ffma2(acc1[6], A1, n67.x); ffma2(acc1[6], X1, s67.x);
        ffma2(acc1[7], A1, n67.y); ffma2(acc1[7], X1, s67.y);
    }

    u64 b[8];
    #pragma unroll
    for (int c = 0; c < 8; c++) b[c] = *(const u64*)(bias + c0 + 2 * c);

    int rlo = row0 + r0;
    if (rlo < n) {
        float* op = out + (size_t)rlo * D + c0;
        #pragma unroll
        for (int c = 0; c < 8; c += 2) {
            ulonglong2 st;
            st.x = add2(acc0[c], b[c]);
            st.y = add2(acc0[c + 1], b[c + 1]);
            *(ulonglong2*)(op + 2 * c) = st;
        }
    }
    if (rlo + 1 < n) {
        float* op = out + (size_t)(rlo + 1) * D + c0;
        #pragma unroll
        for (int c = 0; c < 8; c += 2) {
            ulonglong2 st;
            st.x = add2(acc1[c], b[c]);
            st.y = add2(acc1[c + 1], b[c + 1]);
            *(ulonglong2*)(op + 2 * c) = st;
        }
    }
}

// ---------------------------------------------------------------------------
// launch: histscan(1) scatter(2) agg(3) dual_gemm(4 = profiled slot)
// ---------------------------------------------------------------------------
extern "C" void kernel_launch(void* const* d_in, const int* in_sizes, int n_in,
                              void* d_out, int out_size) {
    const float* x    = (const float*)d_in[0];
    const int*   src  = (const int*)d_in[1];
    const int*   dst  = (const int*)d_in[2];
    const float* w    = (const float*)d_in[3];
    const float* Wn   = (const float*)d_in[4];
    const float* Ws   = (const float*)d_in[5];
    const float* bias = (const float*)d_in[6];
    float* out = (float*)d_out;

    const int n = in_sizes[0] / D;
    const int E = in_sizes[3];
    const int blk = 256;
    const int nb = ((n + 1) + SCHUNK - 1) / SCHUNK;   // 98 for n=100000

    histscan_kernel<<<nb, blk>>>(dst, n, E);
    {
        int nt = (E + 1) / 2;
        scatter_kernel<<<(nt + blk - 1) / blk, blk>>>(src, dst, w, E);
    }
    {
        int warps_per_blk = blk / 32;
        int grid = (n + warps_per_blk - 1) / warps_per_blk;
        agg_kernel<<<grid, blk>>>(x, n);
    }
    {
        size_t smem = 2ull * 128 * RSTR * sizeof(float);  // 67,584 B
        cudaFuncSetAttribute(dual_gemm_kernel,
                             cudaFuncAttributeMaxDynamicSharedMemorySize,
                             (int)smem);
        int grid = (n + BM - 1) / BM;
        dual_gemm_kernel<<<grid, 256, smem>>>(x, Wn, Ws, bias, out, n);
    }
}